// round 11
// baseline (speedup 1.0000x reference)
#include <cuda_runtime.h>
#include <math.h>

#define NPTS     4096
#define NB       16
#define NCLOUD   32
#define NBINS    256
#define SORT_TPB 256
#define MAIN_TPB 256
#define BLK_PER_PAIR 16
#define MAIN_GRID (NCLOUD * BLK_PER_PAIR)   // 512 blocks, 8 warps each
// warp handles 32 consecutive sorted queries (1/lane); 128 chunks per pair.

__device__ __align__(16) float g_sx[NCLOUD][NPTS];
__device__ __align__(16) float g_sy[NCLOUD][NPTS];
__device__ __align__(16) float g_sz[NCLOUD][NPTS];
__device__ __align__(16) float g_su[NCLOUD][NPTS];
__device__ int   g_binstart[NCLOUD][NBINS + 1];
__device__ float g_zmin[NCLOUD];
__device__ float g_binw[NCLOUD];
__device__ float g_accum;       // zero at entry/exit of every launch
__device__ unsigned g_count;    // zero at entry/exit of every launch

typedef unsigned long long u64;

static __device__ __forceinline__ u64 bcast2(float v) {
    u64 r;
    asm("mov.b64 %0, {%1, %1};" : "=l"(r) : "f"(v));
    return r;
}
static __device__ __forceinline__ void unpack2(u64 v, float &lo, float &hi) {
    asm("mov.b64 {%0, %1}, %2;" : "=f"(lo), "=f"(hi) : "l"(v));
}
static __device__ __forceinline__ u64 fma2(u64 a, u64 b, u64 c) {
    u64 d;
    asm("fma.rn.f32x2 %0, %1, %2, %3;" : "=l"(d) : "l"(a), "l"(b), "l"(c));
    return d;
}

// ---------------- sort kernel: bucket each cloud by z into NBINS bins -------
__global__ void __launch_bounds__(SORT_TPB) sort_kernel(const float* __restrict__ tpl,
                                                        const float* __restrict__ src) {
    const int c = blockIdx.x;
    const float* P = (c < NB) ? (tpl + (size_t)c * NPTS * 3)
                              : (src + (size_t)(c - NB) * NPTS * 3);
    __shared__ float rmin[SORT_TPB / 32], rmax[SORT_TPB / 32];
    __shared__ int hist[NBINS];
    __shared__ int scan_a[NBINS], scan_b[NBINS];
    __shared__ int boff[NBINS + 1];
    __shared__ float s_zmin, s_inv;

    const int tid = threadIdx.x;
    float mn = 3.4e38f, mx = -3.4e38f;
    for (int p = tid; p < NPTS; p += SORT_TPB) {
        float z = P[3 * p + 2];
        mn = fminf(mn, z);
        mx = fmaxf(mx, z);
    }
#pragma unroll
    for (int o = 16; o; o >>= 1) {
        mn = fminf(mn, __shfl_xor_sync(0xffffffffu, mn, o));
        mx = fmaxf(mx, __shfl_xor_sync(0xffffffffu, mx, o));
    }
    if ((tid & 31) == 0) { rmin[tid >> 5] = mn; rmax[tid >> 5] = mx; }
    for (int k = tid; k < NBINS; k += SORT_TPB) hist[k] = 0;
    __syncthreads();
    if (tid == 0) {
        float zmin = rmin[0], zmax = rmax[0];
        for (int w = 1; w < SORT_TPB / 32; w++) {
            zmin = fminf(zmin, rmin[w]);
            zmax = fmaxf(zmax, rmax[w]);
        }
        float binw = fmaxf((zmax - zmin) / NBINS, 1e-30f);
        s_zmin = zmin;
        s_inv = 1.0f / binw;
        g_zmin[c] = zmin;
        g_binw[c] = binw;
    }
    __syncthreads();
    const float zmin = s_zmin, inv = s_inv;

    for (int p = tid; p < NPTS; p += SORT_TPB) {
        float z = P[3 * p + 2];
        int bn = min(max((int)((z - zmin) * inv), 0), NBINS - 1);
        atomicAdd(&hist[bn], 1);
    }
    __syncthreads();

    for (int k = tid; k < NBINS; k += SORT_TPB) scan_a[k] = hist[k];
    __syncthreads();
    int* cur = scan_a;
    int* nxt = scan_b;
#pragma unroll
    for (int off = 1; off < NBINS; off <<= 1) {
        for (int k = tid; k < NBINS; k += SORT_TPB)
            nxt[k] = (k >= off) ? cur[k] + cur[k - off] : cur[k];
        __syncthreads();
        int* t = cur; cur = nxt; nxt = t;
    }
    for (int k = tid; k < NBINS; k += SORT_TPB) boff[k] = cur[k] - hist[k];
    if (tid == 0) boff[NBINS] = NPTS;
    __syncthreads();
    for (int k = tid; k < NBINS; k += SORT_TPB) hist[k] = 0;
    __syncthreads();

    for (int p = tid; p < NPTS; p += SORT_TPB) {
        float x = P[3 * p + 0], y = P[3 * p + 1], z = P[3 * p + 2];
        int bn = min(max((int)((z - zmin) * inv), 0), NBINS - 1);
        int idx = boff[bn] + atomicAdd(&hist[bn], 1);
        g_sx[c][idx] = x;
        g_sy[c][idx] = y;
        g_sz[c][idx] = z;
        g_su[c][idx] = x * x + y * y + z * z;
    }
    for (int k = tid; k <= NBINS; k += SORT_TPB) g_binstart[c][k] = boff[k];
}

// ---------- main: smem scan, batched expansion, striped chunk->block map ----
__global__ void __launch_bounds__(MAIN_TPB, 3) chamfer_main(float* __restrict__ out) {
    extern __shared__ float sm[];
    float* sx = sm;
    float* sy = sm + NPTS;
    float* sz = sm + 2 * NPTS;
    float* su = sm + 3 * NPTS;
    int* sbin = (int*)(sm + 4 * NPTS);
    float* red = (float*)(sbin + NBINS + 1);

    const int tid = threadIdx.x;
    const int b = blockIdx.x;
    const int pair = b >> 4;                  // 0..31
    const int blk  = b & 15;
    const int dir = pair >> 4;
    const int batch = pair & 15;
    const int qcl = (dir == 0) ? batch : NB + batch;
    const int dcl = (dir == 0) ? NB + batch : batch;

    for (int p = tid; p < NPTS; p += MAIN_TPB) {
        sx[p] = g_sx[dcl][p];
        sy[p] = g_sy[dcl][p];
        sz[p] = g_sz[dcl][p];
        su[p] = g_su[dcl][p];
    }
    for (int k = tid; k <= NBINS; k += MAIN_TPB) sbin[k] = g_binstart[dcl][k];
    __syncthreads();

    const float zmin = g_zmin[dcl];
    const float binw = g_binw[dcl];
    const float invw = 1.0f / binw;

    const int warp = tid >> 5, lane = tid & 31;
    // striped mapping: block's 8 warps take chunks {blk, blk+16, ..., blk+112}
    const int chunk = warp * BLK_PER_PAIR + blk;    // 0..127
    const int q = chunk * 32 + lane;

    const float qz = g_sz[qcl][q];
    const float qu = g_su[qcl][q];
    const u64 pqx = bcast2(-2.0f * g_sx[qcl][q]);
    const u64 pqy = bcast2(-2.0f * g_sy[qcl][q]);
    const u64 pqz = bcast2(-2.0f * qz);

    float wlo = qz, whi = qz;
#pragma unroll
    for (int o = 16; o; o >>= 1) {
        wlo = fminf(wlo, __shfl_xor_sync(0xffffffffu, wlo, o));
        whi = fmaxf(whi, __shfl_xor_sync(0xffffffffu, whi, o));
    }
    int lo = min(max((int)((wlo - zmin) * invw), 0), NBINS - 1);
    int hi = min(max((int)((whi - zmin) * invw), 0), NBINS - 1);

    float bA = 3.4e38f, bB = 3.4e38f;
    const ulonglong2* vx = (const ulonglong2*)sx;
    const ulonglong2* vy = (const ulonglong2*)sy;
    const ulonglong2* vz = (const ulonglong2*)sz;
    const ulonglong2* vu = (const ulonglong2*)su;

    auto scan = [&](int a, int e) {
        int j1 = (e + 3) >> 2;
#pragma unroll 2
        for (int j = a >> 2; j < j1; j++) {
            ulonglong2 bx = vx[j], by = vy[j], bz = vz[j], bu = vu[j];
            u64 a01 = fma2(pqz, bz.x, bu.x);
            a01 = fma2(pqy, by.x, a01);
            a01 = fma2(pqx, bx.x, a01);
            u64 a23 = fma2(pqz, bz.y, bu.y);
            a23 = fma2(pqy, by.y, a23);
            a23 = fma2(pqx, bx.y, a23);
            float l0, h0, l1, h1;
            unpack2(a01, l0, h0);
            unpack2(a23, l1, h1);
            bA = fminf(bA, fminf(l0, l1));
            bB = fminf(bB, fminf(h0, h1));
        }
    };

    // initial window: bins spanned by the warp's 32 queries
    scan(sbin[lo], sbin[hi + 1]);

    // batched expansion to radius r = sqrt(warp_max(best dist^2))
    while (true) {
        float m = qu + fminf(bA, bB);
#pragma unroll
        for (int o = 16; o; o >>= 1) m = fmaxf(m, __shfl_xor_sync(0xffffffffu, m, o));
        m = fmaxf(m, 0.0f);
        float r = sqrtf(m) * 1.0001f + 1e-12f;
        int nlo = max(min((int)((wlo - r - zmin) * invw), NBINS - 1), 0);
        int nhi = min(max((int)((whi + r - zmin) * invw), 0), NBINS - 1);
        bool grewL = nlo < lo, grewR = nhi > hi;
        if (!grewL && !grewR) break;
        if (grewL) { scan(sbin[nlo], sbin[lo]); lo = nlo; }
        if (grewR) { scan(sbin[hi + 1], sbin[nhi + 1]); hi = nhi; }
    }

    float s = sqrtf(fmaxf(qu + fminf(bA, bB), 0.0f));

    // block reduction (8 warps)
#pragma unroll
    for (int o = 16; o; o >>= 1) s += __shfl_xor_sync(0xffffffffu, s, o);
    if (lane == 0) red[warp] = s;
    __syncthreads();
    if (tid == 0) {
        float t = 0.0f;
#pragma unroll
        for (int w = 0; w < MAIN_TPB / 32; w++) t += red[w];
        atomicAdd(&g_accum, t);
        __threadfence();
        unsigned old = atomicAdd(&g_count, 1u);
        if (old == MAIN_GRID - 1) {
            __threadfence();
            float total = atomicAdd(&g_accum, 0.0f);
            out[0] = total * (1.0f / 131072.0f);   // / (2*16*4096)
            g_accum = 0.0f;
            __threadfence();
            atomicExch(&g_count, 0u);
        }
    }
}

extern "C" void kernel_launch(void* const* d_in, const int* in_sizes, int n_in,
                              void* d_out, int out_size) {
    const float* tpl = (const float*)d_in[0];
    const float* src = (const float*)d_in[1];
    (void)in_sizes; (void)n_in; (void)out_size;

    const int smem = 4 * NPTS * (int)sizeof(float)
                   + (NBINS + 1) * (int)sizeof(int)
                   + (MAIN_TPB / 32) * (int)sizeof(float);
    cudaFuncSetAttribute(chamfer_main, cudaFuncAttributeMaxDynamicSharedMemorySize, smem);

    sort_kernel<<<NCLOUD, SORT_TPB>>>(tpl, src);
    chamfer_main<<<MAIN_GRID, MAIN_TPB, smem>>>((float*)d_out);
}

// round 12
// speedup vs baseline: 1.2985x; 1.2985x over previous
#include <cuda_runtime.h>
#include <math.h>

#define NPTS     4096
#define NB       16
#define NCLOUD   32
#define NBINS    128
#define SORT_TPB 512
#define MAIN_TPB 256
#define KQ       4
#define BLK_PER_PAIR 4
#define MAIN_GRID (NCLOUD * BLK_PER_PAIR)   // 128 blocks, 8 warps, 128 q/warp

__device__ __align__(16) float g_sx[NCLOUD][NPTS];
__device__ __align__(16) float g_sy[NCLOUD][NPTS];
__device__ __align__(16) float g_sz[NCLOUD][NPTS];
__device__ __align__(16) float g_su[NCLOUD][NPTS];
__device__ __align__(16) float4 g_pts[NCLOUD][NPTS];   // sorted (x,y,z,|p|^2)
__device__ int   g_binstart[NCLOUD][NBINS + 1];
__device__ float g_zmin[NCLOUD];
__device__ float g_binw[NCLOUD];
__device__ float g_accum;       // zero at entry/exit of every launch
__device__ unsigned g_count;    // zero at entry/exit of every launch

typedef unsigned long long u64;

static __device__ __forceinline__ u64 bcast2(float v) {
    u64 r;
    asm("mov.b64 %0, {%1, %1};" : "=l"(r) : "f"(v));
    return r;
}
static __device__ __forceinline__ void unpack2(u64 v, float &lo, float &hi) {
    asm("mov.b64 {%0, %1}, %2;" : "=f"(lo), "=f"(hi) : "l"(v));
}
static __device__ __forceinline__ u64 fma2(u64 a, u64 b, u64 c) {
    u64 d;
    asm("fma.rn.f32x2 %0, %1, %2, %3;" : "=l"(d) : "l"(a), "l"(b), "l"(c));
    return d;
}

// ------------- sort kernel: smem-staged z-bucketing of each cloud -----------
__global__ void __launch_bounds__(SORT_TPB) sort_kernel(const float* __restrict__ tpl,
                                                        const float* __restrict__ src) {
    extern __shared__ float stg[];              // [3*NPTS] staged cloud
    __shared__ int hist[NBINS];
    __shared__ int scan_a[NBINS], scan_b[NBINS];
    __shared__ int boff[NBINS + 1];
    __shared__ float rmin[SORT_TPB / 32], rmax[SORT_TPB / 32];
    __shared__ float s_zmin, s_inv;

    const int c = blockIdx.x;
    const float* P = (c < NB) ? (tpl + (size_t)c * NPTS * 3)
                              : (src + (size_t)(c - NB) * NPTS * 3);
    const int tid = threadIdx.x;

    // coalesced float4 staging: 3*NPTS floats = 3*NPTS/4 float4s
    const float4* P4 = (const float4*)P;
    float4* S4 = (float4*)stg;
    for (int i = tid; i < 3 * NPTS / 4; i += SORT_TPB) S4[i] = P4[i];
    if (tid < NBINS) hist[tid] = 0;
    __syncthreads();

    float mn = 3.4e38f, mx = -3.4e38f;
    for (int p = tid; p < NPTS; p += SORT_TPB) {
        float z = stg[3 * p + 2];
        mn = fminf(mn, z);
        mx = fmaxf(mx, z);
    }
#pragma unroll
    for (int o = 16; o; o >>= 1) {
        mn = fminf(mn, __shfl_xor_sync(0xffffffffu, mn, o));
        mx = fmaxf(mx, __shfl_xor_sync(0xffffffffu, mx, o));
    }
    if ((tid & 31) == 0) { rmin[tid >> 5] = mn; rmax[tid >> 5] = mx; }
    __syncthreads();
    if (tid == 0) {
        float zmin = rmin[0], zmax = rmax[0];
        for (int w = 1; w < SORT_TPB / 32; w++) {
            zmin = fminf(zmin, rmin[w]);
            zmax = fmaxf(zmax, rmax[w]);
        }
        float binw = fmaxf((zmax - zmin) / NBINS, 1e-30f);
        s_zmin = zmin;
        s_inv = 1.0f / binw;
        g_zmin[c] = zmin;
        g_binw[c] = binw;
    }
    __syncthreads();
    const float zmin = s_zmin, inv = s_inv;

    for (int p = tid; p < NPTS; p += SORT_TPB) {
        float z = stg[3 * p + 2];
        int bn = min(max((int)((z - zmin) * inv), 0), NBINS - 1);
        atomicAdd(&hist[bn], 1);
    }
    __syncthreads();

    if (tid < NBINS) scan_a[tid] = hist[tid];
    __syncthreads();
    int* cur = scan_a;
    int* nxt = scan_b;
#pragma unroll
    for (int off = 1; off < NBINS; off <<= 1) {
        if (tid < NBINS)
            nxt[tid] = (tid >= off) ? cur[tid] + cur[tid - off] : cur[tid];
        __syncthreads();
        int* t = cur; cur = nxt; nxt = t;
    }
    if (tid < NBINS) boff[tid] = cur[tid] - hist[tid];
    if (tid == 0) boff[NBINS] = NPTS;
    __syncthreads();
    if (tid < NBINS) hist[tid] = 0;
    __syncthreads();

    for (int p = tid; p < NPTS; p += SORT_TPB) {
        float x = stg[3 * p + 0], y = stg[3 * p + 1], z = stg[3 * p + 2];
        int bn = min(max((int)((z - zmin) * inv), 0), NBINS - 1);
        int idx = boff[bn] + atomicAdd(&hist[bn], 1);
        g_pts[c][idx] = make_float4(x, y, z, x * x + y * y + z * z);
    }
    for (int k = tid; k <= NBINS; k += SORT_TPB) g_binstart[c][k] = boff[k];
}

// ------ main: smem scan, K=4 queries/lane (8 FFMA2 chains), striped map -----
__global__ void __launch_bounds__(MAIN_TPB) chamfer_main(float* __restrict__ out) {
    extern __shared__ float sm[];
    float* sx = sm;
    float* sy = sm + NPTS;
    float* sz = sm + 2 * NPTS;
    float* su = sm + 3 * NPTS;
    int* sbin = (int*)(sm + 4 * NPTS);
    float* red = (float*)(sbin + NBINS + 1);

    const int tid = threadIdx.x;
    const int b = blockIdx.x;
    const int pair = b >> 2;                  // 0..31
    const int blk  = b & 3;
    const int dir = pair >> 4;
    const int batch = pair & 15;
    const int qcl = (dir == 0) ? batch : NB + batch;
    const int dcl = (dir == 0) ? NB + batch : batch;

    for (int p = tid; p < NPTS; p += MAIN_TPB) {
        float4 v = g_pts[dcl][p];
        sx[p] = v.x; sy[p] = v.y; sz[p] = v.z; su[p] = v.w;
    }
    for (int k = tid; k <= NBINS; k += MAIN_TPB) sbin[k] = g_binstart[dcl][k];
    __syncthreads();

    const float zmin = g_zmin[dcl];
    const float binw = g_binw[dcl];
    const float invw = 1.0f / binw;

    const int warp = tid >> 5, lane = tid & 31;
    // striped: block's 8 warps take chunks {blk, blk+4, ..., blk+28} (128 q each)
    const int chunk = warp * BLK_PER_PAIR + blk;    // 0..31
    const int qbase = chunk * 128;

    u64 qx2[KQ], qy2[KQ], qz2[KQ];
    float qu[KQ], qzv[KQ];
#pragma unroll
    for (int k = 0; k < KQ; k++) {
        float4 v = g_pts[qcl][qbase + k * 32 + lane];
        qx2[k] = bcast2(-2.0f * v.x);
        qy2[k] = bcast2(-2.0f * v.y);
        qz2[k] = bcast2(-2.0f * v.z);
        qzv[k] = v.z;
        qu[k] = v.w;
    }

    float wlo = qzv[0], whi = qzv[0];
#pragma unroll
    for (int k = 1; k < KQ; k++) {
        wlo = fminf(wlo, qzv[k]);
        whi = fmaxf(whi, qzv[k]);
    }
#pragma unroll
    for (int o = 16; o; o >>= 1) {
        wlo = fminf(wlo, __shfl_xor_sync(0xffffffffu, wlo, o));
        whi = fmaxf(whi, __shfl_xor_sync(0xffffffffu, whi, o));
    }
    int lo = min(max((int)((wlo - zmin) * invw), 0), NBINS - 1);
    int hi = min(max((int)((whi - zmin) * invw), 0), NBINS - 1);

    float bA[KQ], bB[KQ];
#pragma unroll
    for (int k = 0; k < KQ; k++) { bA[k] = 3.4e38f; bB[k] = 3.4e38f; }

    const ulonglong2* vx = (const ulonglong2*)sx;
    const ulonglong2* vy = (const ulonglong2*)sy;
    const ulonglong2* vz = (const ulonglong2*)sz;
    const ulonglong2* vu = (const ulonglong2*)su;

    auto scan = [&](int a, int e) {
        int j1 = (e + 3) >> 2;
#pragma unroll 2
        for (int j = a >> 2; j < j1; j++) {
            ulonglong2 bx = vx[j], by = vy[j], bz = vz[j], bu = vu[j];
#pragma unroll
            for (int k = 0; k < KQ; k++) {
                u64 a01 = fma2(qz2[k], bz.x, bu.x);
                a01 = fma2(qy2[k], by.x, a01);
                a01 = fma2(qx2[k], bx.x, a01);
                u64 a23 = fma2(qz2[k], bz.y, bu.y);
                a23 = fma2(qy2[k], by.y, a23);
                a23 = fma2(qx2[k], bx.y, a23);
                float l0, h0, l1, h1;
                unpack2(a01, l0, h0);
                unpack2(a23, l1, h1);
                bA[k] = fminf(bA[k], fminf(l0, l1));
                bB[k] = fminf(bB[k], fminf(h0, h1));
            }
        }
    };

    // initial window: bins spanned by the warp's 128 queries
    scan(sbin[lo], sbin[hi + 1]);

    // batched expansion to radius r = sqrt(warp_max(best dist^2))
    while (true) {
        float m = qu[0] + fminf(bA[0], bB[0]);
#pragma unroll
        for (int k = 1; k < KQ; k++)
            m = fmaxf(m, qu[k] + fminf(bA[k], bB[k]));
#pragma unroll
        for (int o = 16; o; o >>= 1) m = fmaxf(m, __shfl_xor_sync(0xffffffffu, m, o));
        m = fmaxf(m, 0.0f);
        float r = sqrtf(m) * 1.0001f + 1e-12f;
        int nlo = max(min((int)((wlo - r - zmin) * invw), NBINS - 1), 0);
        int nhi = min(max((int)((whi + r - zmin) * invw), 0), NBINS - 1);
        bool grewL = nlo < lo, grewR = nhi > hi;
        if (!grewL && !grewR) break;
        if (grewL) { scan(sbin[nlo], sbin[lo]); lo = nlo; }
        if (grewR) { scan(sbin[hi + 1], sbin[nhi + 1]); hi = nhi; }
    }

    float s = 0.0f;
#pragma unroll
    for (int k = 0; k < KQ; k++)
        s += sqrtf(fmaxf(qu[k] + fminf(bA[k], bB[k]), 0.0f));

    // block reduction (8 warps)
#pragma unroll
    for (int o = 16; o; o >>= 1) s += __shfl_xor_sync(0xffffffffu, s, o);
    if (lane == 0) red[warp] = s;
    __syncthreads();
    if (tid == 0) {
        float t = 0.0f;
#pragma unroll
        for (int w = 0; w < MAIN_TPB / 32; w++) t += red[w];
        atomicAdd(&g_accum, t);
        __threadfence();
        unsigned old = atomicAdd(&g_count, 1u);
        if (old == MAIN_GRID - 1) {
            __threadfence();
            float total = atomicAdd(&g_accum, 0.0f);
            out[0] = total * (1.0f / 131072.0f);   // / (2*16*4096)
            g_accum = 0.0f;
            __threadfence();
            atomicExch(&g_count, 0u);
        }
    }
}

extern "C" void kernel_launch(void* const* d_in, const int* in_sizes, int n_in,
                              void* d_out, int out_size) {
    const float* tpl = (const float*)d_in[0];
    const float* src = (const float*)d_in[1];
    (void)in_sizes; (void)n_in; (void)out_size;

    const int sort_smem = 3 * NPTS * (int)sizeof(float);
    cudaFuncSetAttribute(sort_kernel, cudaFuncAttributeMaxDynamicSharedMemorySize, sort_smem);

    const int main_smem = 4 * NPTS * (int)sizeof(float)
                        + (NBINS + 1) * (int)sizeof(int)
                        + (MAIN_TPB / 32) * (int)sizeof(float);
    cudaFuncSetAttribute(chamfer_main, cudaFuncAttributeMaxDynamicSharedMemorySize, main_smem);

    sort_kernel<<<NCLOUD, SORT_TPB, sort_smem>>>(tpl, src);
    chamfer_main<<<MAIN_GRID, MAIN_TPB, main_smem>>>((float*)d_out);
}

// round 13
// speedup vs baseline: 1.5916x; 1.2257x over previous
#include <cuda_runtime.h>
#include <math.h>

#define NPTS     4096
#define NB       16
#define NCLOUD   32
#define NBINS    128
#define MARGIN   3
#define SORT_TPB 512
#define MAIN_TPB 256
#define BLK_PER_PAIR 8
#define MAIN_GRID (NCLOUD * BLK_PER_PAIR)   // 256 blocks, 8 warps, 64 q/warp

__device__ __align__(16) float4 g_pts[NCLOUD][NPTS];   // sorted (x,y,z,|p|^2)
__device__ int   g_binstart[NCLOUD][NBINS + 1];
__device__ float g_zmin[NCLOUD];
__device__ float g_binw[NCLOUD];
__device__ float g_accum;       // zero at entry/exit of every launch
__device__ unsigned g_count;    // zero at entry/exit of every launch

typedef unsigned long long u64;

static __device__ __forceinline__ u64 bcast2(float v) {
    u64 r;
    asm("mov.b64 %0, {%1, %1};" : "=l"(r) : "f"(v));
    return r;
}
static __device__ __forceinline__ void unpack2(u64 v, float &lo, float &hi) {
    asm("mov.b64 {%0, %1}, %2;" : "=f"(lo), "=f"(hi) : "l"(v));
}
static __device__ __forceinline__ u64 fma2(u64 a, u64 b, u64 c) {
    u64 d;
    asm("fma.rn.f32x2 %0, %1, %2, %3;" : "=l"(d) : "l"(a), "l"(b), "l"(c));
    return d;
}

// ------------- sort kernel: smem-staged z-bucketing of each cloud -----------
__global__ void __launch_bounds__(SORT_TPB) sort_kernel(const float* __restrict__ tpl,
                                                        const float* __restrict__ src) {
    extern __shared__ float stg[];              // [3*NPTS] staged cloud
    __shared__ int hist[NBINS];
    __shared__ int scan_a[NBINS], scan_b[NBINS];
    __shared__ int boff[NBINS + 1];
    __shared__ float rmin[SORT_TPB / 32], rmax[SORT_TPB / 32];
    __shared__ float s_zmin, s_inv;

    const int c = blockIdx.x;
    const float* P = (c < NB) ? (tpl + (size_t)c * NPTS * 3)
                              : (src + (size_t)(c - NB) * NPTS * 3);
    const int tid = threadIdx.x;

    const float4* P4 = (const float4*)P;
    float4* S4 = (float4*)stg;
    for (int i = tid; i < 3 * NPTS / 4; i += SORT_TPB) S4[i] = P4[i];
    if (tid < NBINS) hist[tid] = 0;
    __syncthreads();

    float mn = 3.4e38f, mx = -3.4e38f;
    for (int p = tid; p < NPTS; p += SORT_TPB) {
        float z = stg[3 * p + 2];
        mn = fminf(mn, z);
        mx = fmaxf(mx, z);
    }
#pragma unroll
    for (int o = 16; o; o >>= 1) {
        mn = fminf(mn, __shfl_xor_sync(0xffffffffu, mn, o));
        mx = fmaxf(mx, __shfl_xor_sync(0xffffffffu, mx, o));
    }
    if ((tid & 31) == 0) { rmin[tid >> 5] = mn; rmax[tid >> 5] = mx; }
    __syncthreads();
    if (tid == 0) {
        float zmin = rmin[0], zmax = rmax[0];
        for (int w = 1; w < SORT_TPB / 32; w++) {
            zmin = fminf(zmin, rmin[w]);
            zmax = fmaxf(zmax, rmax[w]);
        }
        float binw = fmaxf((zmax - zmin) / NBINS, 1e-30f);
        s_zmin = zmin;
        s_inv = 1.0f / binw;
        g_zmin[c] = zmin;
        g_binw[c] = binw;
    }
    __syncthreads();
    const float zmin = s_zmin, inv = s_inv;

    for (int p = tid; p < NPTS; p += SORT_TPB) {
        float z = stg[3 * p + 2];
        int bn = min(max((int)((z - zmin) * inv), 0), NBINS - 1);
        atomicAdd(&hist[bn], 1);
    }
    __syncthreads();

    if (tid < NBINS) scan_a[tid] = hist[tid];
    __syncthreads();
    int* cur = scan_a;
    int* nxt = scan_b;
#pragma unroll
    for (int off = 1; off < NBINS; off <<= 1) {
        if (tid < NBINS)
            nxt[tid] = (tid >= off) ? cur[tid] + cur[tid - off] : cur[tid];
        __syncthreads();
        int* t = cur; cur = nxt; nxt = t;
    }
    if (tid < NBINS) boff[tid] = cur[tid] - hist[tid];
    if (tid == 0) boff[NBINS] = NPTS;
    __syncthreads();
    if (tid < NBINS) hist[tid] = 0;
    __syncthreads();

    for (int p = tid; p < NPTS; p += SORT_TPB) {
        float x = stg[3 * p + 0], y = stg[3 * p + 1], z = stg[3 * p + 2];
        int bn = min(max((int)((z - zmin) * inv), 0), NBINS - 1);
        int idx = boff[bn] + atomicAdd(&hist[bn], 1);
        g_pts[c][idx] = make_float4(x, y, z, x * x + y * y + z * z);
    }
    for (int k = tid; k <= NBINS; k += SORT_TPB) g_binstart[c][k] = boff[k];
}

// -------- main: smem scan, KQ=2, margin pre-scan + rare expansion -----------
__global__ void __launch_bounds__(MAIN_TPB, 3) chamfer_main(float* __restrict__ out) {
    extern __shared__ float sm[];
    float* sx = sm;
    float* sy = sm + NPTS;
    float* sz = sm + 2 * NPTS;
    float* su = sm + 3 * NPTS;
    int* sbin = (int*)(sm + 4 * NPTS);
    float* red = (float*)(sbin + NBINS + 1);

    const int tid = threadIdx.x;
    const int b = blockIdx.x;
    const int pair = b >> 3;                  // 0..31
    const int blk  = b & 7;
    const int dir = pair >> 4;
    const int batch = pair & 15;
    const int qcl = (dir == 0) ? batch : NB + batch;
    const int dcl = (dir == 0) ? NB + batch : batch;

    for (int p = tid; p < NPTS; p += MAIN_TPB) {
        float4 v = g_pts[dcl][p];
        sx[p] = v.x; sy[p] = v.y; sz[p] = v.z; su[p] = v.w;
    }
    for (int k = tid; k <= NBINS; k += MAIN_TPB) sbin[k] = g_binstart[dcl][k];
    __syncthreads();

    const float zmin = g_zmin[dcl];
    const float binw = g_binw[dcl];
    const float invw = 1.0f / binw;

    const int warp = tid >> 5, lane = tid & 31;
    // striped: block's 8 warps take chunks {blk, blk+8, ..., blk+56} (64 q each)
    const int chunk = warp * BLK_PER_PAIR + blk;    // 0..63
    const int q0 = chunk * 64 + lane;
    const int q1 = q0 + 32;

    float4 v0 = g_pts[qcl][q0];
    float4 v1 = g_pts[qcl][q1];
    const float qz0 = v0.z, qu0 = v0.w;
    const float qz1 = v1.z, qu1 = v1.w;
    const u64 pqx0 = bcast2(-2.0f * v0.x);
    const u64 pqy0 = bcast2(-2.0f * v0.y);
    const u64 pqz0 = bcast2(-2.0f * qz0);
    const u64 pqx1 = bcast2(-2.0f * v1.x);
    const u64 pqy1 = bcast2(-2.0f * v1.y);
    const u64 pqz1 = bcast2(-2.0f * qz1);

    float wlo = fminf(qz0, qz1), whi = fmaxf(qz0, qz1);
#pragma unroll
    for (int o = 16; o; o >>= 1) {
        wlo = fminf(wlo, __shfl_xor_sync(0xffffffffu, wlo, o));
        whi = fmaxf(whi, __shfl_xor_sync(0xffffffffu, whi, o));
    }
    // margin pre-scan: include expected-NN-radius halo so the first (long,
    // coherent) scan is near-final and expansion rounds are rare.
    int lo = min(max((int)((wlo - zmin) * invw) - MARGIN, 0), NBINS - 1);
    int hi = min(max((int)((whi - zmin) * invw) + MARGIN, 0), NBINS - 1);

    float b0A = 3.4e38f, b0B = 3.4e38f, b1A = 3.4e38f, b1B = 3.4e38f;
    const ulonglong2* vx = (const ulonglong2*)sx;
    const ulonglong2* vy = (const ulonglong2*)sy;
    const ulonglong2* vz = (const ulonglong2*)sz;
    const ulonglong2* vu = (const ulonglong2*)su;

    auto scan = [&](int a, int e) {
        int j1 = (e + 3) >> 2;
#pragma unroll 2
        for (int j = a >> 2; j < j1; j++) {
            ulonglong2 bx = vx[j], by = vy[j], bz = vz[j], bu = vu[j];
            u64 a01 = fma2(pqz0, bz.x, bu.x);
            a01 = fma2(pqy0, by.x, a01);
            a01 = fma2(pqx0, bx.x, a01);
            u64 a23 = fma2(pqz0, bz.y, bu.y);
            a23 = fma2(pqy0, by.y, a23);
            a23 = fma2(pqx0, bx.y, a23);
            u64 c01 = fma2(pqz1, bz.x, bu.x);
            c01 = fma2(pqy1, by.x, c01);
            c01 = fma2(pqx1, bx.x, c01);
            u64 c23 = fma2(pqz1, bz.y, bu.y);
            c23 = fma2(pqy1, by.y, c23);
            c23 = fma2(pqx1, bx.y, c23);
            float l0, h0, l1, h1;
            unpack2(a01, l0, h0);
            unpack2(a23, l1, h1);
            b0A = fminf(b0A, fminf(l0, l1));
            b0B = fminf(b0B, fminf(h0, h1));
            unpack2(c01, l0, h0);
            unpack2(c23, l1, h1);
            b1A = fminf(b1A, fminf(l0, l1));
            b1B = fminf(b1B, fminf(h0, h1));
        }
    };

    scan(sbin[lo], sbin[hi + 1]);

    // expansion (rarely triggers thanks to the margin)
    while (true) {
        float m = fmaxf(qu0 + fminf(b0A, b0B), qu1 + fminf(b1A, b1B));
#pragma unroll
        for (int o = 16; o; o >>= 1) m = fmaxf(m, __shfl_xor_sync(0xffffffffu, m, o));
        m = fmaxf(m, 0.0f);
        float r = sqrtf(m) * 1.0001f + 1e-12f;
        int nlo = max(min((int)((wlo - r - zmin) * invw), NBINS - 1), 0);
        int nhi = min(max((int)((whi + r - zmin) * invw), 0), NBINS - 1);
        bool grewL = nlo < lo, grewR = nhi > hi;
        if (!grewL && !grewR) break;
        if (grewL) { scan(sbin[nlo], sbin[lo]); lo = nlo; }
        if (grewR) { scan(sbin[hi + 1], sbin[nhi + 1]); hi = nhi; }
    }

    float s = sqrtf(fmaxf(qu0 + fminf(b0A, b0B), 0.0f))
            + sqrtf(fmaxf(qu1 + fminf(b1A, b1B), 0.0f));

    // block reduction (8 warps)
#pragma unroll
    for (int o = 16; o; o >>= 1) s += __shfl_xor_sync(0xffffffffu, s, o);
    if (lane == 0) red[warp] = s;
    __syncthreads();
    if (tid == 0) {
        float t = 0.0f;
#pragma unroll
        for (int w = 0; w < MAIN_TPB / 32; w++) t += red[w];
        atomicAdd(&g_accum, t);
        __threadfence();
        unsigned old = atomicAdd(&g_count, 1u);
        if (old == MAIN_GRID - 1) {
            __threadfence();
            float total = atomicAdd(&g_accum, 0.0f);
            out[0] = total * (1.0f / 131072.0f);   // / (2*16*4096)
            g_accum = 0.0f;
            __threadfence();
            atomicExch(&g_count, 0u);
        }
    }
}

extern "C" void kernel_launch(void* const* d_in, const int* in_sizes, int n_in,
                              void* d_out, int out_size) {
    const float* tpl = (const float*)d_in[0];
    const float* src = (const float*)d_in[1];
    (void)in_sizes; (void)n_in; (void)out_size;

    const int sort_smem = 3 * NPTS * (int)sizeof(float);
    cudaFuncSetAttribute(sort_kernel, cudaFuncAttributeMaxDynamicSharedMemorySize, sort_smem);

    const int main_smem = 4 * NPTS * (int)sizeof(float)
                        + (NBINS + 1) * (int)sizeof(int)
                        + (MAIN_TPB / 32) * (int)sizeof(float);
    cudaFuncSetAttribute(chamfer_main, cudaFuncAttributeMaxDynamicSharedMemorySize, main_smem);

    sort_kernel<<<NCLOUD, SORT_TPB, sort_smem>>>(tpl, src);
    chamfer_main<<<MAIN_GRID, MAIN_TPB, main_smem>>>((float*)d_out);
}

// round 14
// speedup vs baseline: 1.6381x; 1.0292x over previous
#include <cuda_runtime.h>
#include <math.h>

#define NPTS     4096
#define NB       16
#define NCLOUD   32
#define NBINS    128
#define IDXMARGIN 192
#define SORT_TPB 512
#define MAIN_TPB 256
#define BLK_PER_PAIR 8
#define MAIN_GRID (NCLOUD * BLK_PER_PAIR)   // 256 blocks, 8 warps, 64 q/warp

__device__ __align__(16) float4 g_pts[NCLOUD][NPTS];   // sorted (x,y,z,|p|^2)
__device__ int   g_binstart[NCLOUD][NBINS + 1];
__device__ float g_zmin[NCLOUD];
__device__ float g_binw[NCLOUD];
__device__ float g_accum;       // zero at entry/exit of every launch
__device__ unsigned g_count;    // zero at entry/exit of every launch

typedef unsigned long long u64;

static __device__ __forceinline__ u64 bcast2(float v) {
    u64 r;
    asm("mov.b64 %0, {%1, %1};" : "=l"(r) : "f"(v));
    return r;
}
static __device__ __forceinline__ void unpack2(u64 v, float &lo, float &hi) {
    asm("mov.b64 {%0, %1}, %2;" : "=f"(lo), "=f"(hi) : "l"(v));
}
static __device__ __forceinline__ u64 fma2(u64 a, u64 b, u64 c) {
    u64 d;
    asm("fma.rn.f32x2 %0, %1, %2, %3;" : "=l"(d) : "l"(a), "l"(b), "l"(c));
    return d;
}

// ------------- sort kernel: smem-staged z-bucketing of each cloud -----------
__global__ void __launch_bounds__(SORT_TPB) sort_kernel(const float* __restrict__ tpl,
                                                        const float* __restrict__ src) {
    extern __shared__ float stg[];              // [3*NPTS] staged cloud
    __shared__ int hist[NBINS];
    __shared__ int scan_a[NBINS], scan_b[NBINS];
    __shared__ int boff[NBINS + 1];
    __shared__ float rmin[SORT_TPB / 32], rmax[SORT_TPB / 32];
    __shared__ float s_zmin, s_inv;

    const int c = blockIdx.x;
    const float* P = (c < NB) ? (tpl + (size_t)c * NPTS * 3)
                              : (src + (size_t)(c - NB) * NPTS * 3);
    const int tid = threadIdx.x;

    const float4* P4 = (const float4*)P;
    float4* S4 = (float4*)stg;
    for (int i = tid; i < 3 * NPTS / 4; i += SORT_TPB) S4[i] = P4[i];
    if (tid < NBINS) hist[tid] = 0;
    __syncthreads();

    float mn = 3.4e38f, mx = -3.4e38f;
    for (int p = tid; p < NPTS; p += SORT_TPB) {
        float z = stg[3 * p + 2];
        mn = fminf(mn, z);
        mx = fmaxf(mx, z);
    }
#pragma unroll
    for (int o = 16; o; o >>= 1) {
        mn = fminf(mn, __shfl_xor_sync(0xffffffffu, mn, o));
        mx = fmaxf(mx, __shfl_xor_sync(0xffffffffu, mx, o));
    }
    if ((tid & 31) == 0) { rmin[tid >> 5] = mn; rmax[tid >> 5] = mx; }
    __syncthreads();
    if (tid == 0) {
        float zmin = rmin[0], zmax = rmax[0];
        for (int w = 1; w < SORT_TPB / 32; w++) {
            zmin = fminf(zmin, rmin[w]);
            zmax = fmaxf(zmax, rmax[w]);
        }
        float binw = fmaxf((zmax - zmin) / NBINS, 1e-30f);
        s_zmin = zmin;
        s_inv = 1.0f / binw;
        g_zmin[c] = zmin;
        g_binw[c] = binw;
    }
    __syncthreads();
    const float zmin = s_zmin, inv = s_inv;

    for (int p = tid; p < NPTS; p += SORT_TPB) {
        float z = stg[3 * p + 2];
        int bn = min(max((int)((z - zmin) * inv), 0), NBINS - 1);
        atomicAdd(&hist[bn], 1);
    }
    __syncthreads();

    if (tid < NBINS) scan_a[tid] = hist[tid];
    __syncthreads();
    int* cur = scan_a;
    int* nxt = scan_b;
#pragma unroll
    for (int off = 1; off < NBINS; off <<= 1) {
        if (tid < NBINS)
            nxt[tid] = (tid >= off) ? cur[tid] + cur[tid - off] : cur[tid];
        __syncthreads();
        int* t = cur; cur = nxt; nxt = t;
    }
    if (tid < NBINS) boff[tid] = cur[tid] - hist[tid];
    if (tid == 0) boff[NBINS] = NPTS;
    __syncthreads();
    if (tid < NBINS) hist[tid] = 0;
    __syncthreads();

    for (int p = tid; p < NPTS; p += SORT_TPB) {
        float x = stg[3 * p + 0], y = stg[3 * p + 1], z = stg[3 * p + 2];
        int bn = min(max((int)((z - zmin) * inv), 0), NBINS - 1);
        int idx = boff[bn] + atomicAdd(&hist[bn], 1);
        g_pts[c][idx] = make_float4(x, y, z, x * x + y * y + z * z);
    }
    for (int k = tid; k <= NBINS; k += SORT_TPB) g_binstart[c][k] = boff[k];
}

// ---- main: smem scan, KQ=2, index-space margin + coverage-based expansion --
__global__ void __launch_bounds__(MAIN_TPB, 3) chamfer_main(float* __restrict__ out) {
    extern __shared__ float sm[];
    float* sx = sm;
    float* sy = sm + NPTS;
    float* sz = sm + 2 * NPTS;
    float* su = sm + 3 * NPTS;
    int* sbin = (int*)(sm + 4 * NPTS);
    float* red = (float*)(sbin + NBINS + 1);

    const int tid = threadIdx.x;
    const int b = blockIdx.x;
    const int pair = b >> 3;                  // 0..31
    const int blk  = b & 7;
    const int dir = pair >> 4;
    const int batch = pair & 15;
    const int qcl = (dir == 0) ? batch : NB + batch;
    const int dcl = (dir == 0) ? NB + batch : batch;

    for (int p = tid; p < NPTS; p += MAIN_TPB) {
        float4 v = g_pts[dcl][p];
        sx[p] = v.x; sy[p] = v.y; sz[p] = v.z; su[p] = v.w;
    }
    for (int k = tid; k <= NBINS; k += MAIN_TPB) sbin[k] = g_binstart[dcl][k];
    __syncthreads();

    const float zmin = g_zmin[dcl];
    const float binw = g_binw[dcl];
    const float invw = 1.0f / binw;

    const int warp = tid >> 5, lane = tid & 31;
    // striped: block's 8 warps take chunks {blk, blk+8, ..., blk+56} (64 q each)
    const int chunk = warp * BLK_PER_PAIR + blk;    // 0..63
    const int q0 = chunk * 64 + lane;
    const int q1 = q0 + 32;

    float4 v0 = g_pts[qcl][q0];
    float4 v1 = g_pts[qcl][q1];
    const float qz0 = v0.z, qu0 = v0.w;
    const float qz1 = v1.z, qu1 = v1.w;
    const u64 pqx0 = bcast2(-2.0f * v0.x);
    const u64 pqy0 = bcast2(-2.0f * v0.y);
    const u64 pqz0 = bcast2(-2.0f * qz0);
    const u64 pqx1 = bcast2(-2.0f * v1.x);
    const u64 pqy1 = bcast2(-2.0f * v1.y);
    const u64 pqz1 = bcast2(-2.0f * qz1);

    float wlo = fminf(qz0, qz1), whi = fmaxf(qz0, qz1);
#pragma unroll
    for (int o = 16; o; o >>= 1) {
        wlo = fminf(wlo, __shfl_xor_sync(0xffffffffu, wlo, o));
        whi = fmaxf(whi, __shfl_xor_sync(0xffffffffu, whi, o));
    }
    const int lo = min(max((int)((wlo - zmin) * invw), 0), NBINS - 1);
    const int hi = min(max((int)((whi - zmin) * invw), 0), NBINS - 1);

    float b0A = 3.4e38f, b0B = 3.4e38f, b1A = 3.4e38f, b1B = 3.4e38f;
    const ulonglong2* vx = (const ulonglong2*)sx;
    const ulonglong2* vy = (const ulonglong2*)sy;
    const ulonglong2* vz = (const ulonglong2*)sz;
    const ulonglong2* vu = (const ulonglong2*)su;

    auto scan = [&](int a, int e) {
        int j1 = (e + 3) >> 2;
#pragma unroll 2
        for (int j = a >> 2; j < j1; j++) {
            ulonglong2 bx = vx[j], by = vy[j], bz = vz[j], bu = vu[j];
            u64 a01 = fma2(pqz0, bz.x, bu.x);
            a01 = fma2(pqy0, by.x, a01);
            a01 = fma2(pqx0, bx.x, a01);
            u64 a23 = fma2(pqz0, bz.y, bu.y);
            a23 = fma2(pqy0, by.y, a23);
            a23 = fma2(pqx0, bx.y, a23);
            u64 c01 = fma2(pqz1, bz.x, bu.x);
            c01 = fma2(pqy1, by.x, c01);
            c01 = fma2(pqx1, bx.x, c01);
            u64 c23 = fma2(pqz1, bz.y, bu.y);
            c23 = fma2(pqy1, by.y, c23);
            c23 = fma2(pqx1, bx.y, c23);
            float l0, h0, l1, h1;
            unpack2(a01, l0, h0);
            unpack2(a23, l1, h1);
            b0A = fminf(b0A, fminf(l0, l1));
            b0B = fminf(b0B, fminf(h0, h1));
            unpack2(c01, l0, h0);
            unpack2(c23, l1, h1);
            b1A = fminf(b1A, fminf(l0, l1));
            b1B = fminf(b1B, fminf(h0, h1));
        }
    };

    // initial scan: bins spanned by the queries, plus an index-space margin
    // (density-adaptive: fixed POINT count, not fixed z-width).
    int a0 = max(sbin[lo] - IDXMARGIN, 0);
    int a1 = min(sbin[hi + 1] + IDXMARGIN, NPTS);
    scan(a0, a1);

    // coverage-based expansion: required index range from radius r; scan only
    // the uncovered prefix/suffix. Overlap is harmless (min is idempotent).
    while (true) {
        float m = fmaxf(qu0 + fminf(b0A, b0B), qu1 + fminf(b1A, b1B));
#pragma unroll
        for (int o = 16; o; o >>= 1) m = fmaxf(m, __shfl_xor_sync(0xffffffffu, m, o));
        m = fmaxf(m, 0.0f);
        float r = sqrtf(m) * 1.0001f + 1e-12f;
        int nlo = max(min((int)((wlo - r - zmin) * invw), NBINS - 1), 0);
        int nhi = min(max((int)((whi + r - zmin) * invw), 0), NBINS - 1);
        int need0 = sbin[nlo];
        int need1 = sbin[nhi + 1];
        bool growL = need0 < a0, growR = need1 > a1;
        if (!growL && !growR) break;
        if (growL) { scan(need0, a0); a0 = need0; }
        if (growR) { scan(a1, need1); a1 = need1; }
    }

    float s = sqrtf(fmaxf(qu0 + fminf(b0A, b0B), 0.0f))
            + sqrtf(fmaxf(qu1 + fminf(b1A, b1B), 0.0f));

    // block reduction (8 warps)
#pragma unroll
    for (int o = 16; o; o >>= 1) s += __shfl_xor_sync(0xffffffffu, s, o);
    if (lane == 0) red[warp] = s;
    __syncthreads();
    if (tid == 0) {
        float t = 0.0f;
#pragma unroll
        for (int w = 0; w < MAIN_TPB / 32; w++) t += red[w];
        atomicAdd(&g_accum, t);
        __threadfence();
        unsigned old = atomicAdd(&g_count, 1u);
        if (old == MAIN_GRID - 1) {
            __threadfence();
            float total = atomicAdd(&g_accum, 0.0f);
            out[0] = total * (1.0f / 131072.0f);   // / (2*16*4096)
            g_accum = 0.0f;
            __threadfence();
            atomicExch(&g_count, 0u);
        }
    }
}

extern "C" void kernel_launch(void* const* d_in, const int* in_sizes, int n_in,
                              void* d_out, int out_size) {
    const float* tpl = (const float*)d_in[0];
    const float* src = (const float*)d_in[1];
    (void)in_sizes; (void)n_in; (void)out_size;

    const int sort_smem = 3 * NPTS * (int)sizeof(float);
    cudaFuncSetAttribute(sort_kernel, cudaFuncAttributeMaxDynamicSharedMemorySize, sort_smem);

    const int main_smem = 4 * NPTS * (int)sizeof(float)
                        + (NBINS + 1) * (int)sizeof(int)
                        + (MAIN_TPB / 32) * (int)sizeof(float);
    cudaFuncSetAttribute(chamfer_main, cudaFuncAttributeMaxDynamicSharedMemorySize, main_smem);

    sort_kernel<<<NCLOUD, SORT_TPB, sort_smem>>>(tpl, src);
    chamfer_main<<<MAIN_GRID, MAIN_TPB, main_smem>>>((float*)d_out);
}

// round 15
// speedup vs baseline: 1.6866x; 1.0296x over previous
#include <cuda_runtime.h>
#include <math.h>

#define NPTS     4096
#define NB       16
#define NCLOUD   32
#define NBINS    128
#define IDXMARGIN 192
#define SORT_TPB 512
#define MAIN_TPB 512
#define BLK_PER_PAIR 8
#define MAIN_GRID (NCLOUD * BLK_PER_PAIR)   // 256 blocks, 16 warps (8 chunk-pairs x 2 slices)

__device__ __align__(16) float4 g_pts[NCLOUD][NPTS];   // sorted (x,y,z,|p|^2)
__device__ int   g_binstart[NCLOUD][NBINS + 1];
__device__ float g_zmin[NCLOUD];
__device__ float g_binw[NCLOUD];
__device__ float g_accum;       // zero at entry/exit of every launch
__device__ unsigned g_count;    // zero at entry/exit of every launch

typedef unsigned long long u64;

static __device__ __forceinline__ u64 bcast2(float v) {
    u64 r;
    asm("mov.b64 %0, {%1, %1};" : "=l"(r) : "f"(v));
    return r;
}
static __device__ __forceinline__ void unpack2(u64 v, float &lo, float &hi) {
    asm("mov.b64 {%0, %1}, %2;" : "=f"(lo), "=f"(hi) : "l"(v));
}
static __device__ __forceinline__ u64 fma2(u64 a, u64 b, u64 c) {
    u64 d;
    asm("fma.rn.f32x2 %0, %1, %2, %3;" : "=l"(d) : "l"(a), "l"(b), "l"(c));
    return d;
}

// ------------- sort kernel: smem-staged z-bucketing of each cloud -----------
__global__ void __launch_bounds__(SORT_TPB) sort_kernel(const float* __restrict__ tpl,
                                                        const float* __restrict__ src) {
    extern __shared__ float stg[];              // [3*NPTS] staged cloud
    __shared__ int hist[NBINS];
    __shared__ int scan_a[NBINS], scan_b[NBINS];
    __shared__ int boff[NBINS + 1];
    __shared__ float rmin[SORT_TPB / 32], rmax[SORT_TPB / 32];
    __shared__ float s_zmin, s_inv;

    const int c = blockIdx.x;
    const float* P = (c < NB) ? (tpl + (size_t)c * NPTS * 3)
                              : (src + (size_t)(c - NB) * NPTS * 3);
    const int tid = threadIdx.x;

    const float4* P4 = (const float4*)P;
    float4* S4 = (float4*)stg;
    for (int i = tid; i < 3 * NPTS / 4; i += SORT_TPB) S4[i] = P4[i];
    if (tid < NBINS) hist[tid] = 0;
    __syncthreads();

    float mn = 3.4e38f, mx = -3.4e38f;
    for (int p = tid; p < NPTS; p += SORT_TPB) {
        float z = stg[3 * p + 2];
        mn = fminf(mn, z);
        mx = fmaxf(mx, z);
    }
#pragma unroll
    for (int o = 16; o; o >>= 1) {
        mn = fminf(mn, __shfl_xor_sync(0xffffffffu, mn, o));
        mx = fmaxf(mx, __shfl_xor_sync(0xffffffffu, mx, o));
    }
    if ((tid & 31) == 0) { rmin[tid >> 5] = mn; rmax[tid >> 5] = mx; }
    __syncthreads();
    if (tid == 0) {
        float zmin = rmin[0], zmax = rmax[0];
        for (int w = 1; w < SORT_TPB / 32; w++) {
            zmin = fminf(zmin, rmin[w]);
            zmax = fmaxf(zmax, rmax[w]);
        }
        float binw = fmaxf((zmax - zmin) / NBINS, 1e-30f);
        s_zmin = zmin;
        s_inv = 1.0f / binw;
        g_zmin[c] = zmin;
        g_binw[c] = binw;
    }
    __syncthreads();
    const float zmin = s_zmin, inv = s_inv;

    for (int p = tid; p < NPTS; p += SORT_TPB) {
        float z = stg[3 * p + 2];
        int bn = min(max((int)((z - zmin) * inv), 0), NBINS - 1);
        atomicAdd(&hist[bn], 1);
    }
    __syncthreads();

    if (tid < NBINS) scan_a[tid] = hist[tid];
    __syncthreads();
    int* cur = scan_a;
    int* nxt = scan_b;
#pragma unroll
    for (int off = 1; off < NBINS; off <<= 1) {
        if (tid < NBINS)
            nxt[tid] = (tid >= off) ? cur[tid] + cur[tid - off] : cur[tid];
        __syncthreads();
        int* t = cur; cur = nxt; nxt = t;
    }
    if (tid < NBINS) boff[tid] = cur[tid] - hist[tid];
    if (tid == 0) boff[NBINS] = NPTS;
    __syncthreads();
    if (tid < NBINS) hist[tid] = 0;
    __syncthreads();

    for (int p = tid; p < NPTS; p += SORT_TPB) {
        float x = stg[3 * p + 0], y = stg[3 * p + 1], z = stg[3 * p + 2];
        int bn = min(max((int)((z - zmin) * inv), 0), NBINS - 1);
        int idx = boff[bn] + atomicAdd(&hist[bn], 1);
        g_pts[c][idx] = make_float4(x, y, z, x * x + y * y + z * z);
    }
    for (int k = tid; k <= NBINS; k += SORT_TPB) g_binstart[c][k] = boff[k];
}

// --- main: smem scan, KQ=2, index margin, 2-way db-slice per query chunk ----
__global__ void __launch_bounds__(MAIN_TPB, 2) chamfer_main(float* __restrict__ out) {
    extern __shared__ float sm[];
    float* sx = sm;
    float* sy = sm + NPTS;
    float* sz = sm + 2 * NPTS;
    float* su = sm + 3 * NPTS;
    int* sbin = (int*)(sm + 4 * NPTS);                 // NBINS+1 ints
    float* pmOdd = (float*)(sbin + NBINS + 1);         // [8][64] odd-slice mins
    float* red = pmOdd + 8 * 64;                       // 16 floats

    const int tid = threadIdx.x;
    const int b = blockIdx.x;
    const int pair = b >> 3;                  // 0..31
    const int blk  = b & 7;
    const int dir = pair >> 4;
    const int batch = pair & 15;
    const int qcl = (dir == 0) ? batch : NB + batch;
    const int dcl = (dir == 0) ? NB + batch : batch;

    for (int p = tid; p < NPTS; p += MAIN_TPB) {
        float4 v = g_pts[dcl][p];
        sx[p] = v.x; sy[p] = v.y; sz[p] = v.z; su[p] = v.w;
    }
    for (int k = tid; k <= NBINS; k += MAIN_TPB) sbin[k] = g_binstart[dcl][k];
    __syncthreads();

    const float zmin = g_zmin[dcl];
    const float binw = g_binw[dcl];
    const float invw = 1.0f / binw;

    const int warp = tid >> 5, lane = tid & 31;
    const int wpair = warp >> 1;              // 0..7
    const int slice = warp & 1;               // db parity class
    // striped: chunk-pairs {blk, blk+8, ..., blk+56}, 64 queries each
    const int chunk = wpair * BLK_PER_PAIR + blk;   // 0..63
    const int q0 = chunk * 64 + lane;
    const int q1 = q0 + 32;

    float4 v0 = g_pts[qcl][q0];
    float4 v1 = g_pts[qcl][q1];
    const float qz0 = v0.z, qu0 = v0.w;
    const float qz1 = v1.z, qu1 = v1.w;
    const u64 pqx0 = bcast2(-2.0f * v0.x);
    const u64 pqy0 = bcast2(-2.0f * v0.y);
    const u64 pqz0 = bcast2(-2.0f * qz0);
    const u64 pqx1 = bcast2(-2.0f * v1.x);
    const u64 pqy1 = bcast2(-2.0f * v1.y);
    const u64 pqz1 = bcast2(-2.0f * qz1);

    float wlo = fminf(qz0, qz1), whi = fmaxf(qz0, qz1);
#pragma unroll
    for (int o = 16; o; o >>= 1) {
        wlo = fminf(wlo, __shfl_xor_sync(0xffffffffu, wlo, o));
        whi = fmaxf(whi, __shfl_xor_sync(0xffffffffu, whi, o));
    }
    const int lo = min(max((int)((wlo - zmin) * invw), 0), NBINS - 1);
    const int hi = min(max((int)((whi - zmin) * invw), 0), NBINS - 1);

    float b0A = 3.4e38f, b0B = 3.4e38f, b1A = 3.4e38f, b1B = 3.4e38f;
    const ulonglong2* vx = (const ulonglong2*)sx;
    const ulonglong2* vy = (const ulonglong2*)sy;
    const ulonglong2* vz = (const ulonglong2*)sz;
    const ulonglong2* vu = (const ulonglong2*)su;

    // scan only quads with parity == slice (stride 2): the partner warp covers
    // the other parity; union is exact (each slice's radius >= true radius).
    auto scan = [&](int a, int e) {
        int j0 = a >> 2;
        j0 += (j0 & 1) ^ slice;
        int j1 = (e + 3) >> 2;
        for (int j = j0; j < j1; j += 2) {
            ulonglong2 bx = vx[j], by = vy[j], bz = vz[j], bu = vu[j];
            u64 a01 = fma2(pqz0, bz.x, bu.x);
            a01 = fma2(pqy0, by.x, a01);
            a01 = fma2(pqx0, bx.x, a01);
            u64 a23 = fma2(pqz0, bz.y, bu.y);
            a23 = fma2(pqy0, by.y, a23);
            a23 = fma2(pqx0, bx.y, a23);
            u64 c01 = fma2(pqz1, bz.x, bu.x);
            c01 = fma2(pqy1, by.x, c01);
            c01 = fma2(pqx1, bx.x, c01);
            u64 c23 = fma2(pqz1, bz.y, bu.y);
            c23 = fma2(pqy1, by.y, c23);
            c23 = fma2(pqx1, bx.y, c23);
            float l0, h0, l1, h1;
            unpack2(a01, l0, h0);
            unpack2(a23, l1, h1);
            b0A = fminf(b0A, fminf(l0, l1));
            b0B = fminf(b0B, fminf(h0, h1));
            unpack2(c01, l0, h0);
            unpack2(c23, l1, h1);
            b1A = fminf(b1A, fminf(l0, l1));
            b1B = fminf(b1B, fminf(h0, h1));
        }
    };

    // initial scan: query span + density-adaptive index-space margin
    int a0 = max(sbin[lo] - IDXMARGIN, 0);
    int a1 = min(sbin[hi + 1] + IDXMARGIN, NPTS);
    scan(a0, a1);

    // coverage-based expansion using this slice's (conservative) partial min
    while (true) {
        float m = fmaxf(qu0 + fminf(b0A, b0B), qu1 + fminf(b1A, b1B));
#pragma unroll
        for (int o = 16; o; o >>= 1) m = fmaxf(m, __shfl_xor_sync(0xffffffffu, m, o));
        m = fmaxf(m, 0.0f);
        float r = sqrtf(m) * 1.0001f + 1e-12f;
        int nlo = max(min((int)((wlo - r - zmin) * invw), NBINS - 1), 0);
        int nhi = min(max((int)((whi + r - zmin) * invw), 0), NBINS - 1);
        int need0 = sbin[nlo];
        int need1 = sbin[nhi + 1];
        bool growL = need0 < a0, growR = need1 > a1;
        if (!growL && !growR) break;
        if (growL) { scan(need0, a0); a0 = need0; }
        if (growR) { scan(a1, need1); a1 = need1; }
    }

    // odd slice publishes its partial mins; even slice combines
    if (slice == 1) {
        pmOdd[wpair * 64 + lane]      = fminf(b0A, b0B);
        pmOdd[wpair * 64 + 32 + lane] = fminf(b1A, b1B);
    }
    __syncthreads();

    float s = 0.0f;
    if (slice == 0) {
        float m0 = fminf(fminf(b0A, b0B), pmOdd[wpair * 64 + lane]);
        float m1 = fminf(fminf(b1A, b1B), pmOdd[wpair * 64 + 32 + lane]);
        s = sqrtf(fmaxf(qu0 + m0, 0.0f)) + sqrtf(fmaxf(qu1 + m1, 0.0f));
    }

    // block reduction (16 warps; odd-slice warps contribute 0)
#pragma unroll
    for (int o = 16; o; o >>= 1) s += __shfl_xor_sync(0xffffffffu, s, o);
    if (lane == 0) red[warp] = s;
    __syncthreads();
    if (tid == 0) {
        float t = 0.0f;
#pragma unroll
        for (int w = 0; w < MAIN_TPB / 32; w++) t += red[w];
        atomicAdd(&g_accum, t);
        __threadfence();
        unsigned old = atomicAdd(&g_count, 1u);
        if (old == MAIN_GRID - 1) {
            __threadfence();
            float total = atomicAdd(&g_accum, 0.0f);
            out[0] = total * (1.0f / 131072.0f);   // / (2*16*4096)
            g_accum = 0.0f;
            __threadfence();
            atomicExch(&g_count, 0u);
        }
    }
}

extern "C" void kernel_launch(void* const* d_in, const int* in_sizes, int n_in,
                              void* d_out, int out_size) {
    const float* tpl = (const float*)d_in[0];
    const float* src = (const float*)d_in[1];
    (void)in_sizes; (void)n_in; (void)out_size;

    const int sort_smem = 3 * NPTS * (int)sizeof(float);
    cudaFuncSetAttribute(sort_kernel, cudaFuncAttributeMaxDynamicSharedMemorySize, sort_smem);

    const int main_smem = 4 * NPTS * (int)sizeof(float)
                        + (NBINS + 1) * (int)sizeof(int)
                        + (8 * 64 + MAIN_TPB / 32) * (int)sizeof(float);
    cudaFuncSetAttribute(chamfer_main, cudaFuncAttributeMaxDynamicSharedMemorySize, main_smem);

    sort_kernel<<<NCLOUD, SORT_TPB, sort_smem>>>(tpl, src);
    chamfer_main<<<MAIN_GRID, MAIN_TPB, main_smem>>>((float*)d_out);
}